// round 11
// baseline (speedup 1.0000x reference)
#include <cuda_runtime.h>
#include <cstdint>

#define HW 50176            // 224*224
#define S_BANDS 371
#define LUT_N 1024

// 2*pi*H*C*1e9 * STRESS_MAGNITUDE
#define PHASE_SCALE 15833.626974092555f
#define MIN_INIT 0x7F7FFFFFu   // FLT_MAX bits (inputs are in [0,1])

#define K12_TPB 128
#define MM_BLOCKS 98                     // 98*128 threads, 1 float4 each = 12544
#define ENT_PER_BLK 16                   // LUT entries per block (8 thr/entry)
#define LUT_BLOCKS (LUT_N / ENT_PER_BLK)         // 64
#define K12_BLOCKS (MM_BLOCKS + LUT_BLOCKS)      // 162 x 128thr -> ~1 blk/SM

// stats packed in one 16B struct: one LDG.128 fetches all three + ticket slot
// .x = min bits, .y = max bits, .z = lutmax bits, .w = ticket
static __device__ uint4  g_stats = {MIN_INIT, 0u, 0u, 0u};
static __device__ float4 g_lut[LUT_N];          // {F0, F1, F2, pad}

// ---------------------------------------------------------------------------
// K12: fused min/max + LUT build on disjoint block ranges (128-thr blocks so
// LUT MUFU work spreads ~1 warp/SMSP across the chip).
//   blocks [0,98):    chip-wide min/max of stressmap (atomics on g_stats.x/.y)
//   blocks [98,162):  LUT, 8 threads per entry (<=47-band MUFU chain each).
// Each block fires the PDL trigger as its LAST act, so the dependent pixel
// kernel launches while K12's tail drains.
// ---------------------------------------------------------------------------
__global__ void __launch_bounds__(K12_TPB) k12_kernel(const float* __restrict__ sm,
                                                      const float* __restrict__ ss) {
    const int tid = threadIdx.x;

    if (blockIdx.x < MM_BLOCKS) {
        const int i = blockIdx.x * K12_TPB + tid;      // 0 .. 12543
        float4 v = ((const float4*)sm)[i];
        float mn = fminf(fminf(v.x, v.y), fminf(v.z, v.w));
        float mx = fmaxf(fmaxf(v.x, v.y), fmaxf(v.z, v.w));
        #pragma unroll
        for (int o = 16; o; o >>= 1) {
            mn = fminf(mn, __shfl_xor_sync(0xFFFFFFFFu, mn, o));
            mx = fmaxf(mx, __shfl_xor_sync(0xFFFFFFFFu, mx, o));
        }
        if ((tid & 31) == 0) {
            atomicMin(&g_stats.x, __float_as_uint(mn));
            atomicMax(&g_stats.y, __float_as_uint(mx));
        }
    } else {
        __shared__ float4 tab[S_BANDS];        // {1/lambda, w0, w1, w2}
        __shared__ float  s_a[3][K12_TPB];     // per-thread partials

        for (int s = tid; s < S_BANDS; s += K12_TPB) {
            tab[s] = make_float4(1.0f / (390.0f + (float)s),
                                 ss[3 * s + 0], ss[3 * s + 1], ss[3 * s + 2]);
        }
        __syncthreads();

        const int e = tid & (ENT_PER_BLK - 1);          // entry within block
        const int q = tid >> 4;                         // band octant 0..7
        const int i = (blockIdx.x - MM_BLOCKS) * ENT_PER_BLK + e;   // LUT index
        const float t = (float)i * (PHASE_SCALE / (float)(LUT_N - 1));

        const int s0 = q * 47;
        const int s1 = (q == 7) ? S_BANDS : s0 + 47;    // last octant: 42 bands

        // partial of sum_s w_sc*(1 - cos(t/lam_s)) over this octant
        float a0 = 0.f, a1 = 0.f, a2 = 0.f;
        for (int s = s0; s < s1; s++) {
            float4 v = tab[s];
            float c = 1.0f - __cosf(t * v.x);
            a0 = fmaf(v.y, c, a0);
            a1 = fmaf(v.z, c, a1);
            a2 = fmaf(v.w, c, a2);
        }
        s_a[0][tid] = a0; s_a[1][tid] = a1; s_a[2][tid] = a2;
        __syncthreads();

        if (q == 0) {   // threads 0..15 finalize the block's 16 entries
            float F[3];
            #pragma unroll
            for (int c = 0; c < 3; c++) {
                float acc = s_a[c][e];
                #pragma unroll
                for (int w = 1; w < 8; w++) acc += s_a[c][e + ENT_PER_BLK * w];
                F[c] = 0.5f * acc;
            }
            g_lut[i] = make_float4(F[0], F[1], F[2], 0.f);

            float m = fmaxf(F[0], fmaxf(F[1], F[2]));
            #pragma unroll
            for (int o = 8; o; o >>= 1) m = fmaxf(m, __shfl_xor_sync(0xFFFFu, m, o));
            if (e == 0) atomicMax(&g_stats.z, __float_as_uint(m));
        }
    }

    // PDL early trigger: all this block's global writes are issued above;
    // griddepsync in the secondary guarantees their visibility.
    cudaTriggerProgrammaticLaunchCompletion();
}

// ---------------------------------------------------------------------------
// K3: per-pixel lerp + normalize + store, x2 (float2), PDL-launched.
// Input load issued BEFORE cudaGridDependencySynchronize(); stats fetched by
// every thread (one L1-broadcast LDG.128). Final barrier before the ticket:
// output stores data-depend on the stats, so every thread's stats read is
// consumed before the barrier -> all reads precede the last-block reset.
// ---------------------------------------------------------------------------
__global__ void __launch_bounds__(256) pixel_kernel(const float* __restrict__ sm,
                                                    float* __restrict__ out) {
    const int tid = threadIdx.x;
    const int p2  = blockIdx.x * 256 + tid;          // 0 .. 25087

    const float2 x = ((const float2*)sm)[p2];        // independent of K12

    cudaGridDependencySynchronize();                 // K12's writes now visible

    unsigned sx, sy, sz, swu;
    asm volatile("ld.global.v4.u32 {%0,%1,%2,%3}, [%4];"
                 : "=r"(sx), "=r"(sy), "=r"(sz), "=r"(swu)
                 : "l"(&g_stats) : "memory");        // one LDG.128, L1-bcast
    (void)swu;
    const float mn     = __uint_as_float(sx);
    const float invrng = (float)(LUT_N - 1) / (__uint_as_float(sy) - mn);
    const float inv    = 1.0f / __uint_as_float(sz);

    float r0[2], r1[2], r2[2];
    const float xs[2] = {x.x, x.y};
    #pragma unroll
    for (int k = 0; k < 2; k++) {
        float u = (xs[k] - mn) * invrng;             // 0 .. LUT_N-1
        int   i = (int)u;
        i = (i < 0) ? 0 : ((i > LUT_N - 2) ? LUT_N - 2 : i);
        float fr = u - (float)i;
        float4 a = g_lut[i];
        float4 b = g_lut[i + 1];
        r0[k] = fmaf(fr, b.x - a.x, a.x) * inv;
        r1[k] = fmaf(fr, b.y - a.y, a.y) * inv;
        r2[k] = fmaf(fr, b.z - a.z, a.z) * inv;
    }

    float2* o2 = (float2*)out;
    o2[p2]          = make_float2(r0[0], r0[1]);
    o2[HW / 2 + p2] = make_float2(r1[0], r1[1]);
    o2[HW + p2]     = make_float2(r2[0], r2[1]);

    __syncthreads();   // all threads' stats reads are consumed by now

    // last-one-out reset: every block's reads precede its ticket.
    if (tid == 0) {
        __threadfence();
        unsigned t = atomicAdd(&g_stats.w, 1u);
        if (t == gridDim.x - 1) {
            g_stats.x = MIN_INIT;
            g_stats.y = 0u;
            g_stats.z = 0u;
            g_stats.w = 0u;
            __threadfence();
        }
    }
}

extern "C" void kernel_launch(void* const* d_in, const int* in_sizes, int n_in,
                              void* d_out, int out_size) {
    const float* sm = (const float*)d_in[0];
    const float* ss = (const float*)d_in[1];
    if (in_sizes[0] != HW) {   // defensive: identify by element count
        sm = (const float*)d_in[1];
        ss = (const float*)d_in[0];
    }
    float* out = (float*)d_out;

    k12_kernel<<<K12_BLOCKS, K12_TPB>>>(sm, ss);     // 162 blocks x 128 thr

    // PDL: pixel kernel launches early; orders itself via griddepsync.
    cudaLaunchConfig_t cfg = {};
    cfg.gridDim  = dim3(HW / 2 / 256);               // 98 blocks
    cfg.blockDim = dim3(256);
    cudaLaunchAttribute attr[1];
    attr[0].id = cudaLaunchAttributeProgrammaticStreamSerialization;
    attr[0].val.programmaticStreamSerializationAllowed = 1;
    cfg.attrs = attr;
    cfg.numAttrs = 1;
    cudaLaunchKernelEx(&cfg, pixel_kernel, sm, out);
}

// round 13
// speedup vs baseline: 1.0435x; 1.0435x over previous
#include <cuda_runtime.h>
#include <cstdint>

#define HW 50176            // 224*224
#define S_BANDS 371
#define LUT_N 1024

// 2*pi*H*C*1e9 * STRESS_MAGNITUDE
#define PHASE_SCALE 15833.626974092555f
#define MIN_INIT 0x7F7FFFFFu   // FLT_MAX bits (inputs are in [0,1])

#define MM_BLOCKS 49                     // 49*256 threads, 1 float4 each = 12544
#define ENT_PER_BLK 32                   // LUT entries per block (8 thr/entry)
#define LUT_BLOCKS (LUT_N / ENT_PER_BLK)         // 32
#define K12_BLOCKS (MM_BLOCKS + LUT_BLOCKS)      // 81 blocks, one wave

// stats packed in one 16B struct: one LDG.128 fetches all three + ticket slot
// .x = min bits, .y = max bits, .z = lutmax bits, .w = ticket
static __device__ uint4  g_stats = {MIN_INIT, 0u, 0u, 0u};
static __device__ float4 g_lut[LUT_N];          // {F0, F1, F2, pad}

// ---------------------------------------------------------------------------
// K12: fused min/max + LUT build on disjoint block ranges. 81 blocks -> one
// wave. No explicit PDL trigger (PSS fires implicitly at block completion).
//   blocks [0,49):  chip-wide min/max of stressmap (atomics on g_stats.x/.y)
//   blocks [49,81): LUT, 8 threads per entry (<=47-band MUFU chain each).
// ---------------------------------------------------------------------------
__global__ void __launch_bounds__(256) k12_kernel(const float* __restrict__ sm,
                                                  const float* __restrict__ ss) {
    const int tid = threadIdx.x;

    if (blockIdx.x < MM_BLOCKS) {
        const int i = blockIdx.x * 256 + tid;          // 0 .. 12543
        float4 v = ((const float4*)sm)[i];
        float mn = fminf(fminf(v.x, v.y), fminf(v.z, v.w));
        float mx = fmaxf(fmaxf(v.x, v.y), fmaxf(v.z, v.w));
        #pragma unroll
        for (int o = 16; o; o >>= 1) {
            mn = fminf(mn, __shfl_xor_sync(0xFFFFFFFFu, mn, o));
            mx = fmaxf(mx, __shfl_xor_sync(0xFFFFFFFFu, mx, o));
        }
        if ((tid & 31) == 0) {
            atomicMin(&g_stats.x, __float_as_uint(mn));
            atomicMax(&g_stats.y, __float_as_uint(mx));
        }
    } else {
        __shared__ float4 tab[S_BANDS];        // {1/lambda, w0, w1, w2}
        __shared__ float  s_a[3][256];         // per-thread partials

        for (int s = tid; s < S_BANDS; s += 256) {
            tab[s] = make_float4(1.0f / (390.0f + (float)s),
                                 ss[3 * s + 0], ss[3 * s + 1], ss[3 * s + 2]);
        }
        __syncthreads();

        const int e = tid & (ENT_PER_BLK - 1);          // entry within block
        const int q = tid >> 5;                         // band octant 0..7
        const int i = (blockIdx.x - MM_BLOCKS) * ENT_PER_BLK + e;   // LUT index
        const float t = (float)i * (PHASE_SCALE / (float)(LUT_N - 1));

        const int s0 = q * 47;
        const int s1 = (q == 7) ? S_BANDS : s0 + 47;    // last octant: 42 bands

        // partial of sum_s w_sc*(1 - cos(t/lam_s)) over this octant
        float a0 = 0.f, a1 = 0.f, a2 = 0.f;
        for (int s = s0; s < s1; s++) {
            float4 v = tab[s];
            float c = 1.0f - __cosf(t * v.x);
            a0 = fmaf(v.y, c, a0);
            a1 = fmaf(v.z, c, a1);
            a2 = fmaf(v.w, c, a2);
        }
        s_a[0][tid] = a0; s_a[1][tid] = a1; s_a[2][tid] = a2;
        __syncthreads();

        if (q == 0) {   // warp 0 finalizes the block's 32 entries
            float F[3];
            #pragma unroll
            for (int c = 0; c < 3; c++) {
                float acc = s_a[c][e];
                #pragma unroll
                for (int w = 1; w < 8; w++) acc += s_a[c][e + ENT_PER_BLK * w];
                F[c] = 0.5f * acc;
            }
            g_lut[i] = make_float4(F[0], F[1], F[2], 0.f);

            float m = fmaxf(F[0], fmaxf(F[1], F[2]));
            #pragma unroll
            for (int o = 16; o; o >>= 1) m = fmaxf(m, __shfl_xor_sync(0xFFFFFFFFu, m, o));
            if (e == 0) atomicMax(&g_stats.z, __float_as_uint(m));
        }
    }
}

// ---------------------------------------------------------------------------
// K3: per-pixel lerp + normalize + store, x2 (float2), PDL-launched.
// Input load issued BEFORE cudaGridDependencySynchronize(); stats fetched by
// every thread (one L1-broadcast LDG.128). Final barrier before the ticket:
// output stores data-depend on the stats, so every thread's stats read is
// consumed before the barrier -> all reads precede the last-block reset.
// ---------------------------------------------------------------------------
__global__ void __launch_bounds__(256) pixel_kernel(const float* __restrict__ sm,
                                                    float* __restrict__ out) {
    const int tid = threadIdx.x;
    const int p2  = blockIdx.x * 256 + tid;          // 0 .. 25087

    const float2 x = ((const float2*)sm)[p2];        // independent of K12

    cudaGridDependencySynchronize();                 // K12's writes now visible

    unsigned sx, sy, sz, swu;
    asm volatile("ld.global.v4.u32 {%0,%1,%2,%3}, [%4];"
                 : "=r"(sx), "=r"(sy), "=r"(sz), "=r"(swu)
                 : "l"(&g_stats) : "memory");        // one LDG.128, L1-bcast
    (void)swu;
    const float mn     = __uint_as_float(sx);
    const float invrng = (float)(LUT_N - 1) / (__uint_as_float(sy) - mn);
    const float inv    = 1.0f / __uint_as_float(sz);

    float r0[2], r1[2], r2[2];
    const float xs[2] = {x.x, x.y};
    #pragma unroll
    for (int k = 0; k < 2; k++) {
        float u = (xs[k] - mn) * invrng;             // 0 .. LUT_N-1
        int   i = (int)u;
        i = (i < 0) ? 0 : ((i > LUT_N - 2) ? LUT_N - 2 : i);
        float fr = u - (float)i;
        float4 a = g_lut[i];
        float4 b = g_lut[i + 1];
        r0[k] = fmaf(fr, b.x - a.x, a.x) * inv;
        r1[k] = fmaf(fr, b.y - a.y, a.y) * inv;
        r2[k] = fmaf(fr, b.z - a.z, a.z) * inv;
    }

    float2* o2 = (float2*)out;
    o2[p2]          = make_float2(r0[0], r0[1]);
    o2[HW / 2 + p2] = make_float2(r1[0], r1[1]);
    o2[HW + p2]     = make_float2(r2[0], r2[1]);

    __syncthreads();   // all threads' stats reads are consumed by now

    // last-one-out reset: every block's reads precede its ticket.
    if (tid == 0) {
        __threadfence();
        unsigned t = atomicAdd(&g_stats.w, 1u);
        if (t == gridDim.x - 1) {
            g_stats.x = MIN_INIT;
            g_stats.y = 0u;
            g_stats.z = 0u;
            g_stats.w = 0u;
            __threadfence();
        }
    }
}

extern "C" void kernel_launch(void* const* d_in, const int* in_sizes, int n_in,
                              void* d_out, int out_size) {
    const float* sm = (const float*)d_in[0];
    const float* ss = (const float*)d_in[1];
    if (in_sizes[0] != HW) {   // defensive: identify by element count
        sm = (const float*)d_in[1];
        ss = (const float*)d_in[0];
    }
    float* out = (float*)d_out;

    k12_kernel<<<K12_BLOCKS, 256>>>(sm, ss);         // 81 blocks, one wave

    // PDL: pixel kernel launches early (implicit trigger at K12 block
    // completion); orders itself via griddepsync.
    cudaLaunchConfig_t cfg = {};
    cfg.gridDim  = dim3(HW / 2 / 256);               // 98 blocks
    cfg.blockDim = dim3(256);
    cudaLaunchAttribute attr[1];
    attr[0].id = cudaLaunchAttributeProgrammaticStreamSerialization;
    attr[0].val.programmaticStreamSerializationAllowed = 1;
    cfg.attrs = attr;
    cfg.numAttrs = 1;
    cudaLaunchKernelEx(&cfg, pixel_kernel, sm, out);
}

// round 14
// speedup vs baseline: 1.0500x; 1.0063x over previous
#include <cuda_runtime.h>
#include <cstdint>

#define HW 50176            // 224*224
#define S_BANDS 371
#define LUT_N 512

// 2*pi*H*C*1e9 * STRESS_MAGNITUDE
#define PHASE_SCALE 15833.626974092555f
#define MIN_INIT 0x7F7FFFFFu   // FLT_MAX bits (inputs are in [0,1])

#define MM_BLOCKS 49                     // 49*256 threads, 1 float4 each = 12544
#define ENT_PER_BLK 16                   // LUT entries per block (16 thr/entry)
#define SEG 16                           // band segments per entry
#define BANDS_PER_SEG 24                 // 16*24 = 384 >= 371
#define LUT_BLOCKS (LUT_N / ENT_PER_BLK)         // 32
#define K12_BLOCKS (MM_BLOCKS + LUT_BLOCKS)      // 81 blocks, one wave

// stats packed in one 16B struct: one LDG.128 fetches all three + ticket slot
// .x = min bits, .y = max bits, .z = lutmax bits, .w = ticket
static __device__ uint4  g_stats = {MIN_INIT, 0u, 0u, 0u};
static __device__ float4 g_lut[LUT_N];          // {F0, F1, F2, pad}

// ---------------------------------------------------------------------------
// K12: fused min/max + LUT build on disjoint block ranges. 81 blocks -> one
// wave. Implicit PSS trigger at block completion releases the pixel kernel.
//   blocks [0,49):  chip-wide min/max of stressmap (atomics on g_stats.x/.y)
//   blocks [49,81): LUT, 16 threads per entry (<=24-band MUFU chain each).
// ---------------------------------------------------------------------------
__global__ void __launch_bounds__(256) k12_kernel(const float* __restrict__ sm,
                                                  const float* __restrict__ ss) {
    const int tid = threadIdx.x;

    if (blockIdx.x < MM_BLOCKS) {
        const int i = blockIdx.x * 256 + tid;          // 0 .. 12543
        float4 v = ((const float4*)sm)[i];
        float mn = fminf(fminf(v.x, v.y), fminf(v.z, v.w));
        float mx = fmaxf(fmaxf(v.x, v.y), fmaxf(v.z, v.w));
        #pragma unroll
        for (int o = 16; o; o >>= 1) {
            mn = fminf(mn, __shfl_xor_sync(0xFFFFFFFFu, mn, o));
            mx = fmaxf(mx, __shfl_xor_sync(0xFFFFFFFFu, mx, o));
        }
        if ((tid & 31) == 0) {
            atomicMin(&g_stats.x, __float_as_uint(mn));
            atomicMax(&g_stats.y, __float_as_uint(mx));
        }
    } else {
        __shared__ float4 tab[S_BANDS];        // {1/lambda, w0, w1, w2}
        __shared__ float  s_a[3][256];         // per-thread partials

        for (int s = tid; s < S_BANDS; s += 256) {
            tab[s] = make_float4(1.0f / (390.0f + (float)s),
                                 ss[3 * s + 0], ss[3 * s + 1], ss[3 * s + 2]);
        }
        __syncthreads();

        const int e = tid & (ENT_PER_BLK - 1);          // entry within block
        const int q = tid >> 4;                         // band segment 0..15
        const int i = (blockIdx.x - MM_BLOCKS) * ENT_PER_BLK + e;   // LUT index
        const float t = (float)i * (PHASE_SCALE / (float)(LUT_N - 1));

        const int s0 = q * BANDS_PER_SEG;
        const int s1 = (s0 + BANDS_PER_SEG < S_BANDS) ? s0 + BANDS_PER_SEG : S_BANDS;

        // partial of sum_s w_sc*(1 - cos(t/lam_s)) over this segment
        float a0 = 0.f, a1 = 0.f, a2 = 0.f;
        for (int s = s0; s < s1; s++) {
            float4 v = tab[s];
            float c = 1.0f - __cosf(t * v.x);
            a0 = fmaf(v.y, c, a0);
            a1 = fmaf(v.z, c, a1);
            a2 = fmaf(v.w, c, a2);
        }
        s_a[0][tid] = a0; s_a[1][tid] = a1; s_a[2][tid] = a2;
        __syncthreads();

        if (q == 0) {   // threads 0..15 finalize the block's 16 entries
            float F[3];
            #pragma unroll
            for (int c = 0; c < 3; c++) {
                float acc = s_a[c][e];
                #pragma unroll
                for (int w = 1; w < SEG; w++) acc += s_a[c][e + ENT_PER_BLK * w];
                F[c] = 0.5f * acc;
            }
            g_lut[i] = make_float4(F[0], F[1], F[2], 0.f);

            float m = fmaxf(F[0], fmaxf(F[1], F[2]));
            #pragma unroll
            for (int o = 8; o; o >>= 1) m = fmaxf(m, __shfl_xor_sync(0xFFFFu, m, o));
            if (e == 0) atomicMax(&g_stats.z, __float_as_uint(m));
        }
    }
}

// ---------------------------------------------------------------------------
// K3: per-pixel lerp + normalize + store, x2 (float2), PDL-launched.
// Input load issued BEFORE cudaGridDependencySynchronize(); stats fetched by
// every thread (one L1-broadcast LDG.128). Final barrier before the ticket:
// output stores data-depend on the stats, so every thread's stats read is
// consumed before the barrier -> all reads precede the last-block reset.
// ---------------------------------------------------------------------------
__global__ void __launch_bounds__(256) pixel_kernel(const float* __restrict__ sm,
                                                    float* __restrict__ out) {
    const int tid = threadIdx.x;
    const int p2  = blockIdx.x * 256 + tid;          // 0 .. 25087

    const float2 x = ((const float2*)sm)[p2];        // independent of K12

    cudaGridDependencySynchronize();                 // K12's writes now visible

    unsigned sx, sy, sz, swu;
    asm volatile("ld.global.v4.u32 {%0,%1,%2,%3}, [%4];"
                 : "=r"(sx), "=r"(sy), "=r"(sz), "=r"(swu)
                 : "l"(&g_stats) : "memory");        // one LDG.128, L1-bcast
    (void)swu;
    const float mn     = __uint_as_float(sx);
    const float invrng = (float)(LUT_N - 1) / (__uint_as_float(sy) - mn);
    const float inv    = 1.0f / __uint_as_float(sz);

    float r0[2], r1[2], r2[2];
    const float xs[2] = {x.x, x.y};
    #pragma unroll
    for (int k = 0; k < 2; k++) {
        float u = (xs[k] - mn) * invrng;             // 0 .. LUT_N-1
        int   i = (int)u;
        i = (i < 0) ? 0 : ((i > LUT_N - 2) ? LUT_N - 2 : i);
        float fr = u - (float)i;
        float4 a = g_lut[i];
        float4 b = g_lut[i + 1];
        r0[k] = fmaf(fr, b.x - a.x, a.x) * inv;
        r1[k] = fmaf(fr, b.y - a.y, a.y) * inv;
        r2[k] = fmaf(fr, b.z - a.z, a.z) * inv;
    }

    float2* o2 = (float2*)out;
    o2[p2]          = make_float2(r0[0], r0[1]);
    o2[HW / 2 + p2] = make_float2(r1[0], r1[1]);
    o2[HW + p2]     = make_float2(r2[0], r2[1]);

    __syncthreads();   // all threads' stats reads are consumed by now

    // last-one-out reset: every block's reads precede its ticket.
    if (tid == 0) {
        __threadfence();
        unsigned t = atomicAdd(&g_stats.w, 1u);
        if (t == gridDim.x - 1) {
            g_stats.x = MIN_INIT;
            g_stats.y = 0u;
            g_stats.z = 0u;
            g_stats.w = 0u;
            __threadfence();
        }
    }
}

extern "C" void kernel_launch(void* const* d_in, const int* in_sizes, int n_in,
                              void* d_out, int out_size) {
    const float* sm = (const float*)d_in[0];
    const float* ss = (const float*)d_in[1];
    if (in_sizes[0] != HW) {   // defensive: identify by element count
        sm = (const float*)d_in[1];
        ss = (const float*)d_in[0];
    }
    float* out = (float*)d_out;

    k12_kernel<<<K12_BLOCKS, 256>>>(sm, ss);         // 81 blocks, one wave

    // PDL: pixel kernel launches early (implicit trigger at K12 block
    // completion); orders itself via griddepsync.
    cudaLaunchConfig_t cfg = {};
    cfg.gridDim  = dim3(HW / 2 / 256);               // 98 blocks
    cfg.blockDim = dim3(256);
    cudaLaunchAttribute attr[1];
    attr[0].id = cudaLaunchAttributeProgrammaticStreamSerialization;
    attr[0].val.programmaticStreamSerializationAllowed = 1;
    cfg.attrs = attr;
    cfg.numAttrs = 1;
    cudaLaunchKernelEx(&cfg, pixel_kernel, sm, out);
}

// round 15
// speedup vs baseline: 1.2043x; 1.1470x over previous
#include <cuda_runtime.h>
#include <cstdint>

#define HW 50176            // 224*224
#define S_BANDS 371
#define LUT_N 512

// 2*pi*H*C*1e9 * STRESS_MAGNITUDE
#define PHASE_SCALE 15833.626974092555f

#define MM_BLOCKS 49                     // 49*256 threads, 1 float4 each = 12544
#define ENT_PER_BLK 16                   // LUT entries per block (16 thr/entry)
#define SEG 16                           // band segments per entry
#define BANDS_PER_SEG 24                 // 16*24 = 384 >= 371
#define LUT_BLOCKS (LUT_N / ENT_PER_BLK)         // 32
#define K12_BLOCKS (MM_BLOCKS + LUT_BLOCKS)      // 81 blocks, one wave

// Per-block partial results — plain stores, fully overwritten every replay.
// NO atomics, NO reset logic anywhere.
static __device__ float  g_pmin[MM_BLOCKS];     // block minima
static __device__ float  g_pmax[MM_BLOCKS];     // block maxima
static __device__ float  g_plmax[LUT_BLOCKS];   // per-LUT-block max of F
static __device__ float4 g_lut[LUT_N];          // {F0, F1, F2, pad}

// ---------------------------------------------------------------------------
// K12: fused min/max + LUT build on disjoint block ranges. 81 blocks -> one
// wave. Implicit PSS trigger at block completion releases the pixel kernel.
//   blocks [0,49):  block min/max of stressmap -> g_pmin/g_pmax (plain STG)
//   blocks [49,81): LUT, 16 threads per entry; block lutmax -> g_plmax.
// ---------------------------------------------------------------------------
__global__ void __launch_bounds__(256) k12_kernel(const float* __restrict__ sm,
                                                  const float* __restrict__ ss) {
    const int tid  = threadIdx.x;
    const int lane = tid & 31;
    const int wrp  = tid >> 5;

    if (blockIdx.x < MM_BLOCKS) {
        __shared__ float s_mn[8], s_mx[8];
        const int i = blockIdx.x * 256 + tid;          // 0 .. 12543
        float4 v = ((const float4*)sm)[i];
        float mn = fminf(fminf(v.x, v.y), fminf(v.z, v.w));
        float mx = fmaxf(fmaxf(v.x, v.y), fmaxf(v.z, v.w));
        #pragma unroll
        for (int o = 16; o; o >>= 1) {
            mn = fminf(mn, __shfl_xor_sync(0xFFFFFFFFu, mn, o));
            mx = fmaxf(mx, __shfl_xor_sync(0xFFFFFFFFu, mx, o));
        }
        if (lane == 0) { s_mn[wrp] = mn; s_mx[wrp] = mx; }
        __syncthreads();
        if (tid == 0) {
            float bmn = s_mn[0], bmx = s_mx[0];
            #pragma unroll
            for (int w = 1; w < 8; w++) {
                bmn = fminf(bmn, s_mn[w]);
                bmx = fmaxf(bmx, s_mx[w]);
            }
            g_pmin[blockIdx.x] = bmn;                  // plain stores
            g_pmax[blockIdx.x] = bmx;
        }
    } else {
        __shared__ float4 tab[S_BANDS];        // {1/lambda, w0, w1, w2}
        __shared__ float  s_a[3][256];         // per-thread partials

        for (int s = tid; s < S_BANDS; s += 256) {
            tab[s] = make_float4(1.0f / (390.0f + (float)s),
                                 ss[3 * s + 0], ss[3 * s + 1], ss[3 * s + 2]);
        }
        __syncthreads();

        const int e = tid & (ENT_PER_BLK - 1);          // entry within block
        const int q = tid >> 4;                         // band segment 0..15
        const int i = (blockIdx.x - MM_BLOCKS) * ENT_PER_BLK + e;   // LUT index
        const float t = (float)i * (PHASE_SCALE / (float)(LUT_N - 1));

        const int s0 = q * BANDS_PER_SEG;
        const int s1 = (s0 + BANDS_PER_SEG < S_BANDS) ? s0 + BANDS_PER_SEG : S_BANDS;

        // partial of sum_s w_sc*(1 - cos(t/lam_s)) over this segment
        float a0 = 0.f, a1 = 0.f, a2 = 0.f;
        for (int s = s0; s < s1; s++) {
            float4 v = tab[s];
            float c = 1.0f - __cosf(t * v.x);
            a0 = fmaf(v.y, c, a0);
            a1 = fmaf(v.z, c, a1);
            a2 = fmaf(v.w, c, a2);
        }
        s_a[0][tid] = a0; s_a[1][tid] = a1; s_a[2][tid] = a2;
        __syncthreads();

        if (q == 0) {   // threads 0..15 finalize the block's 16 entries
            float F[3];
            #pragma unroll
            for (int c = 0; c < 3; c++) {
                float acc = s_a[c][e];
                #pragma unroll
                for (int w = 1; w < SEG; w++) acc += s_a[c][e + ENT_PER_BLK * w];
                F[c] = 0.5f * acc;
            }
            g_lut[i] = make_float4(F[0], F[1], F[2], 0.f);

            float m = fmaxf(F[0], fmaxf(F[1], F[2]));
            #pragma unroll
            for (int o = 8; o; o >>= 1) m = fmaxf(m, __shfl_xor_sync(0xFFFFu, m, o));
            if (e == 0) g_plmax[blockIdx.x - MM_BLOCKS] = m;   // plain store
        }
    }
}

// ---------------------------------------------------------------------------
// K3: per-pixel lerp + normalize + store, x2 (float2), PDL-launched.
// Input load issued BEFORE cudaGridDependencySynchronize(). After the sync,
// warps 0..2 reduce the per-block partials (min / max / lutmax) in parallel;
// one smem barrier broadcasts the 3 scalars. No tail work at all.
// ---------------------------------------------------------------------------
__global__ void __launch_bounds__(256) pixel_kernel(const float* __restrict__ sm,
                                                    float* __restrict__ out) {
    __shared__ float s_red[3];     // {min, max, lutmax}
    const int tid  = threadIdx.x;
    const int lane = tid & 31;
    const int wrp  = tid >> 5;
    const int p2   = blockIdx.x * 256 + tid;         // 0 .. 25087

    const float2 x = ((const float2*)sm)[p2];        // independent of K12

    cudaGridDependencySynchronize();                 // K12's writes now visible

    if (wrp == 0) {                                  // reduce 49 block minima
        float v = (lane < MM_BLOCKS) ? g_pmin[lane] : 3.4e38f;
        if (lane + 32 < MM_BLOCKS) v = fminf(v, g_pmin[lane + 32]);
        #pragma unroll
        for (int o = 16; o; o >>= 1) v = fminf(v, __shfl_xor_sync(0xFFFFFFFFu, v, o));
        if (lane == 0) s_red[0] = v;
    } else if (wrp == 1) {                           // reduce 49 block maxima
        float v = (lane < MM_BLOCKS) ? g_pmax[lane] : 0.f;
        if (lane + 32 < MM_BLOCKS) v = fmaxf(v, g_pmax[lane + 32]);
        #pragma unroll
        for (int o = 16; o; o >>= 1) v = fmaxf(v, __shfl_xor_sync(0xFFFFFFFFu, v, o));
        if (lane == 0) s_red[1] = v;
    } else if (wrp == 2) {                           // reduce 32 lut maxima
        float v = g_plmax[lane];
        #pragma unroll
        for (int o = 16; o; o >>= 1) v = fmaxf(v, __shfl_xor_sync(0xFFFFFFFFu, v, o));
        if (lane == 0) s_red[2] = v;
    }
    __syncthreads();

    const float mn     = s_red[0];
    const float invrng = (float)(LUT_N - 1) / (s_red[1] - mn);
    const float inv    = 1.0f / s_red[2];

    float r0[2], r1[2], r2[2];
    const float xs[2] = {x.x, x.y};
    #pragma unroll
    for (int k = 0; k < 2; k++) {
        float u = (xs[k] - mn) * invrng;             // 0 .. LUT_N-1
        int   i = (int)u;
        i = (i < 0) ? 0 : ((i > LUT_N - 2) ? LUT_N - 2 : i);
        float fr = u - (float)i;
        float4 a = g_lut[i];
        float4 b = g_lut[i + 1];
        r0[k] = fmaf(fr, b.x - a.x, a.x) * inv;
        r1[k] = fmaf(fr, b.y - a.y, a.y) * inv;
        r2[k] = fmaf(fr, b.z - a.z, a.z) * inv;
    }

    float2* o2 = (float2*)out;
    o2[p2]          = make_float2(r0[0], r0[1]);
    o2[HW / 2 + p2] = make_float2(r1[0], r1[1]);
    o2[HW + p2]     = make_float2(r2[0], r2[1]);
    // no tail: nothing to reset, kernel ends at the last store.
}

extern "C" void kernel_launch(void* const* d_in, const int* in_sizes, int n_in,
                              void* d_out, int out_size) {
    const float* sm = (const float*)d_in[0];
    const float* ss = (const float*)d_in[1];
    if (in_sizes[0] != HW) {   // defensive: identify by element count
        sm = (const float*)d_in[1];
        ss = (const float*)d_in[0];
    }
    float* out = (float*)d_out;

    k12_kernel<<<K12_BLOCKS, 256>>>(sm, ss);         // 81 blocks, one wave

    // PDL: pixel kernel launches early (implicit trigger at K12 block
    // completion); orders itself via griddepsync.
    cudaLaunchConfig_t cfg = {};
    cfg.gridDim  = dim3(HW / 2 / 256);               // 98 blocks
    cfg.blockDim = dim3(256);
    cudaLaunchAttribute attr[1];
    attr[0].id = cudaLaunchAttributeProgrammaticStreamSerialization;
    attr[0].val.programmaticStreamSerializationAllowed = 1;
    cfg.attrs = attr;
    cfg.numAttrs = 1;
    cudaLaunchKernelEx(&cfg, pixel_kernel, sm, out);
}

// round 16
// speedup vs baseline: 1.2824x; 1.0649x over previous
#include <cuda_runtime.h>
#include <cstdint>

#define HW 50176            // 224*224
#define S_BANDS 371
#define LUT_N 512

// 2*pi*H*C*1e9 * STRESS_MAGNITUDE
#define PHASE_SCALE 15833.626974092555f

#define MM_BLOCKS 49                     // 49*256 threads, 1 float4 each = 12544
#define ENT_PER_BLK 8                    // LUT entries per block (32 thr/entry)
#define SEG 32                           // band segments per entry
#define BANDS_PER_SEG 12                 // 32*12 = 384 >= 371
#define LUT_BLOCKS (LUT_N / ENT_PER_BLK)         // 64
#define K12_BLOCKS (MM_BLOCKS + LUT_BLOCKS)      // 113 blocks, one wave

// Per-block partial results — plain stores, fully overwritten every replay.
// NO atomics, NO reset logic anywhere.
static __device__ float  g_pmin[MM_BLOCKS];     // block minima
static __device__ float  g_pmax[MM_BLOCKS];     // block maxima
static __device__ float  g_plmax[LUT_BLOCKS];   // per-LUT-block max of F
static __device__ float4 g_lut[LUT_N];          // {F0, F1, F2, pad}

// ---------------------------------------------------------------------------
// K12: fused min/max + LUT build on disjoint block ranges. 113 blocks -> one
// wave. Implicit PSS trigger at block completion releases the pixel kernel.
//   blocks [0,49):   block min/max of stressmap -> g_pmin/g_pmax (plain STG)
//   blocks [49,113): LUT, 32 threads per entry (<=12-band MUFU chain each);
//                    shfl folds 4 segment-groups per warp, then one 8-way add.
// ---------------------------------------------------------------------------
__global__ void __launch_bounds__(256) k12_kernel(const float* __restrict__ sm,
                                                  const float* __restrict__ ss) {
    const int tid  = threadIdx.x;
    const int lane = tid & 31;
    const int wrp  = tid >> 5;

    if (blockIdx.x < MM_BLOCKS) {
        __shared__ float s_mn[8], s_mx[8];
        const int i = blockIdx.x * 256 + tid;          // 0 .. 12543
        float4 v = ((const float4*)sm)[i];
        float mn = fminf(fminf(v.x, v.y), fminf(v.z, v.w));
        float mx = fmaxf(fmaxf(v.x, v.y), fmaxf(v.z, v.w));
        #pragma unroll
        for (int o = 16; o; o >>= 1) {
            mn = fminf(mn, __shfl_xor_sync(0xFFFFFFFFu, mn, o));
            mx = fmaxf(mx, __shfl_xor_sync(0xFFFFFFFFu, mx, o));
        }
        if (lane == 0) { s_mn[wrp] = mn; s_mx[wrp] = mx; }
        __syncthreads();
        if (tid == 0) {
            float bmn = s_mn[0], bmx = s_mx[0];
            #pragma unroll
            for (int w = 1; w < 8; w++) {
                bmn = fminf(bmn, s_mn[w]);
                bmx = fmaxf(bmx, s_mx[w]);
            }
            g_pmin[blockIdx.x] = bmn;                  // plain stores
            g_pmax[blockIdx.x] = bmx;
        }
    } else {
        __shared__ float4 tab[S_BANDS];        // {1/lambda, w0, w1, w2}
        __shared__ float  s_a[3][64];          // 8 warps x 8 entries partials

        for (int s = tid; s < S_BANDS; s += 256) {
            tab[s] = make_float4(1.0f / (390.0f + (float)s),
                                 ss[3 * s + 0], ss[3 * s + 1], ss[3 * s + 2]);
        }
        __syncthreads();

        const int e = tid & (ENT_PER_BLK - 1);          // entry within block 0..7
        const int q = tid >> 3;                         // band segment 0..31
        const int i = (blockIdx.x - MM_BLOCKS) * ENT_PER_BLK + e;   // LUT index
        const float t = (float)i * (PHASE_SCALE / (float)(LUT_N - 1));

        int s0 = q * BANDS_PER_SEG;
        int s1 = s0 + BANDS_PER_SEG;
        if (s0 > S_BANDS) s0 = S_BANDS;
        if (s1 > S_BANDS) s1 = S_BANDS;

        // partial of sum_s w_sc*(1 - cos(t/lam_s)) over this segment
        float a0 = 0.f, a1 = 0.f, a2 = 0.f;
        for (int s = s0; s < s1; s++) {
            float4 v = tab[s];
            float c = 1.0f - __cosf(t * v.x);
            a0 = fmaf(v.y, c, a0);
            a1 = fmaf(v.z, c, a1);
            a2 = fmaf(v.w, c, a2);
        }
        // fold the 4 segment-groups inside each warp (lanes differing in bits 3,4)
        #pragma unroll
        for (int o = 8; o <= 16; o <<= 1) {
            a0 += __shfl_xor_sync(0xFFFFFFFFu, a0, o);
            a1 += __shfl_xor_sync(0xFFFFFFFFu, a1, o);
            a2 += __shfl_xor_sync(0xFFFFFFFFu, a2, o);
        }
        if (lane < ENT_PER_BLK) {       // lane==entry: per-warp partial
            s_a[0][wrp * 8 + lane] = a0;
            s_a[1][wrp * 8 + lane] = a1;
            s_a[2][wrp * 8 + lane] = a2;
        }
        __syncthreads();

        if (tid < ENT_PER_BLK) {        // threads 0..7 finalize 8 entries
            float F[3];
            #pragma unroll
            for (int c = 0; c < 3; c++) {
                float acc = s_a[c][tid];
                #pragma unroll
                for (int w = 1; w < 8; w++) acc += s_a[c][w * 8 + tid];
                F[c] = 0.5f * acc;
            }
            const int ii = (blockIdx.x - MM_BLOCKS) * ENT_PER_BLK + tid;
            g_lut[ii] = make_float4(F[0], F[1], F[2], 0.f);

            float m = fmaxf(F[0], fmaxf(F[1], F[2]));
            #pragma unroll
            for (int o = 4; o; o >>= 1) m = fmaxf(m, __shfl_xor_sync(0xFFu, m, o));
            if (tid == 0) g_plmax[blockIdx.x - MM_BLOCKS] = m;   // plain store
        }
    }
}

// ---------------------------------------------------------------------------
// K3: per-pixel lerp + normalize + store, x2 (float2), PDL-launched.
// Input load issued BEFORE cudaGridDependencySynchronize(). After the sync,
// warps 0..2 reduce the per-block partials (min / max / lutmax) in parallel;
// one smem barrier broadcasts the 3 scalars. No tail work at all.
// ---------------------------------------------------------------------------
__global__ void __launch_bounds__(256) pixel_kernel(const float* __restrict__ sm,
                                                    float* __restrict__ out) {
    __shared__ float s_red[3];     // {min, max, lutmax}
    const int tid  = threadIdx.x;
    const int lane = tid & 31;
    const int wrp  = tid >> 5;
    const int p2   = blockIdx.x * 256 + tid;         // 0 .. 25087

    const float2 x = ((const float2*)sm)[p2];        // independent of K12

    cudaGridDependencySynchronize();                 // K12's writes now visible

    if (wrp == 0) {                                  // reduce 49 block minima
        float v = (lane < MM_BLOCKS) ? g_pmin[lane] : 3.4e38f;
        if (lane + 32 < MM_BLOCKS) v = fminf(v, g_pmin[lane + 32]);
        #pragma unroll
        for (int o = 16; o; o >>= 1) v = fminf(v, __shfl_xor_sync(0xFFFFFFFFu, v, o));
        if (lane == 0) s_red[0] = v;
    } else if (wrp == 1) {                           // reduce 49 block maxima
        float v = (lane < MM_BLOCKS) ? g_pmax[lane] : 0.f;
        if (lane + 32 < MM_BLOCKS) v = fmaxf(v, g_pmax[lane + 32]);
        #pragma unroll
        for (int o = 16; o; o >>= 1) v = fmaxf(v, __shfl_xor_sync(0xFFFFFFFFu, v, o));
        if (lane == 0) s_red[1] = v;
    } else if (wrp == 2) {                           // reduce 64 lut maxima
        float v = fmaxf(g_plmax[lane], g_plmax[lane + 32]);
        #pragma unroll
        for (int o = 16; o; o >>= 1) v = fmaxf(v, __shfl_xor_sync(0xFFFFFFFFu, v, o));
        if (lane == 0) s_red[2] = v;
    }
    __syncthreads();

    const float mn     = s_red[0];
    const float invrng = (float)(LUT_N - 1) / (s_red[1] - mn);
    const float inv    = 1.0f / s_red[2];

    float r0[2], r1[2], r2[2];
    const float xs[2] = {x.x, x.y};
    #pragma unroll
    for (int k = 0; k < 2; k++) {
        float u = (xs[k] - mn) * invrng;             // 0 .. LUT_N-1
        int   i = (int)u;
        i = (i < 0) ? 0 : ((i > LUT_N - 2) ? LUT_N - 2 : i);
        float fr = u - (float)i;
        float4 a = g_lut[i];
        float4 b = g_lut[i + 1];
        r0[k] = fmaf(fr, b.x - a.x, a.x) * inv;
        r1[k] = fmaf(fr, b.y - a.y, a.y) * inv;
        r2[k] = fmaf(fr, b.z - a.z, a.z) * inv;
    }

    float2* o2 = (float2*)out;
    o2[p2]          = make_float2(r0[0], r0[1]);
    o2[HW / 2 + p2] = make_float2(r1[0], r1[1]);
    o2[HW + p2]     = make_float2(r2[0], r2[1]);
    // no tail: nothing to reset, kernel ends at the last store.
}

extern "C" void kernel_launch(void* const* d_in, const int* in_sizes, int n_in,
                              void* d_out, int out_size) {
    const float* sm = (const float*)d_in[0];
    const float* ss = (const float*)d_in[1];
    if (in_sizes[0] != HW) {   // defensive: identify by element count
        sm = (const float*)d_in[1];
        ss = (const float*)d_in[0];
    }
    float* out = (float*)d_out;

    k12_kernel<<<K12_BLOCKS, 256>>>(sm, ss);         // 113 blocks, one wave

    // PDL: pixel kernel launches early (implicit trigger at K12 block
    // completion); orders itself via griddepsync.
    cudaLaunchConfig_t cfg = {};
    cfg.gridDim  = dim3(HW / 2 / 256);               // 98 blocks
    cfg.blockDim = dim3(256);
    cudaLaunchAttribute attr[1];
    attr[0].id = cudaLaunchAttributeProgrammaticStreamSerialization;
    attr[0].val.programmaticStreamSerializationAllowed = 1;
    cfg.attrs = attr;
    cfg.numAttrs = 1;
    cudaLaunchKernelEx(&cfg, pixel_kernel, sm, out);
}